// round 9
// baseline (speedup 1.0000x reference)
#include <cuda_runtime.h>
#include <cuda_bf16.h>
#include <mma.h>
#include <cstdint>

using namespace nvcuda;

// ---------------------------------------------------------------------------
// TripletHardLoss: loss = mean(relu(max_{same}(dist) - min_{diff}(dist) + 0.3))
// dist[i][j] = sqrt(max(||xi||^2 + ||xj||^2 - 2 xi.xj, 0))
// bf16 WMMA Gram. R9: 64x64 warp tiles (2x fewer LDS bytes/MMA), BM=128
// BN=256 CTA tile, 1 CTA/SM (255 regs), rectangular triangular coverage
// (blocks i >= 2j), 3-stage cp.async, one barrier per K-stage.
// ---------------------------------------------------------------------------

#define MAX_N 4096
#define MAX_D 2048

__device__ float           g_sq[MAX_N];
__device__ unsigned int    g_ap[MAX_N];
__device__ unsigned int    g_an[MAX_N];
__device__ int             g_lbl[MAX_N];
__device__ int             g_is64;
__device__ __nv_bfloat16   g_xb[(size_t)MAX_N * MAX_D];

// ---- tiling ----
#define BM 128
#define BN 256
#define KT 64                 // K per smem stage
#define LDA 72                // bf16 stage row stride (pad 8), 144B
#define LDC 260               // fp32 C row stride (%4==0)
#define NSTAGE 3
#define A_ELEMS (BM * LDA)                 // 9216
#define B_ELEMS (BN * LDA)                 // 18432
#define STAGE_ELEMS (A_ELEMS + B_ELEMS)    // 27648 elems = 55296 B
// smem: stages [3] = 165888B; C tile (128*260*4 = 133120B) aliases; meta after
#define OFF_META (NSTAGE * STAGE_ELEMS * 2)
#define SMEM_BYTES (OFF_META + (128 + 128 + 256 + 256) * 4)

__device__ __forceinline__ uint32_t smem_u32(const void* p) {
    uint32_t a;
    asm("{ .reg .u64 t; cvta.to.shared.u64 t, %1; cvt.u32.u64 %0, t; }"
        : "=r"(a) : "l"(p));
    return a;
}
__device__ __forceinline__ void cp_async16(uint32_t dst, const void* src) {
    asm volatile("cp.async.cg.shared.global [%0], [%1], 16;"
                 :: "r"(dst), "l"(src) : "memory");
}

// ---- kernel -1: detect label dtype ----
__global__ void k_detect(const int* __restrict__ Yi) {
    if (threadIdx.x == 0) {
        int nz = 0;
#pragma unroll
        for (int i = 0; i < 64; i++) nz |= Yi[2 * i + 1];
        g_is64 = (nz == 0) ? 1 : 0;
    }
}

// ---- kernel 0: row sum-of-squares + init + label narrow ----
__global__ void k_rowsq(const float* __restrict__ X,
                        const void* __restrict__ Y,
                        int n, int d) {
    int row = blockIdx.x;
    const float4* xr = reinterpret_cast<const float4*>(X + (size_t)row * d);
    int nv = d >> 2;
    float s = 0.f;
    for (int i = threadIdx.x; i < nv; i += blockDim.x) {
        float4 v = xr[i];
        s += v.x * v.x + v.y * v.y + v.z * v.z + v.w * v.w;
    }
    __shared__ float sh[32];
    for (int o = 16; o > 0; o >>= 1) s += __shfl_xor_sync(0xffffffffu, s, o);
    if ((threadIdx.x & 31) == 0) sh[threadIdx.x >> 5] = s;
    __syncthreads();
    if (threadIdx.x < 32) {
        float v = (threadIdx.x < (blockDim.x >> 5)) ? sh[threadIdx.x] : 0.f;
        for (int o = 16; o > 0; o >>= 1) v += __shfl_xor_sync(0xffffffffu, v, o);
        if (threadIdx.x == 0) {
            g_sq[row]  = v;
            g_ap[row]  = 0u;
            g_an[row]  = 0x7F800000u;
            g_lbl[row] = g_is64
                ? (int)reinterpret_cast<const long long*>(Y)[row]
                : reinterpret_cast<const int*>(Y)[row];
        }
    }
}

// ---- kernel 1: X (fp32) -> g_xb (bf16) ----
__global__ void k_tobf16(const float* __restrict__ X, int total4) {
    int stride = gridDim.x * blockDim.x;
    __nv_bfloat162* dst = reinterpret_cast<__nv_bfloat162*>(g_xb);
    for (int idx = blockIdx.x * blockDim.x + threadIdx.x; idx < total4;
         idx += stride) {
        float4 v = reinterpret_cast<const float4*>(X)[idx];
        dst[idx * 2 + 0] = __nv_bfloat162(__float2bfloat16(v.x),
                                          __float2bfloat16(v.y));
        dst[idx * 2 + 1] = __nv_bfloat162(__float2bfloat16(v.z),
                                          __float2bfloat16(v.w));
    }
}

// ---- kernel 2: 64x64-warp-tile bf16 WMMA Gram + masked max/min ----
__global__ __launch_bounds__(256, 1)
void k_wmma(int n, int d) {
    extern __shared__ __align__(16) char smem[];
    __nv_bfloat16* stage = reinterpret_cast<__nv_bfloat16*>(smem);
    float* Cs  = reinterpret_cast<float*>(smem);
    float* sqm = reinterpret_cast<float*>(smem + OFF_META);
    int*   lbm = reinterpret_cast<int*>(sqm + 128);
    float* sqn = reinterpret_cast<float*>(lbm + 128);
    int*   lbn = reinterpret_cast<int*>(sqn + 256);

    // rectangular triangular decode: keep blocks with i >= 2j
    int b = blockIdx.x;
    int j = 0, off = 0;
    while (off + (32 - 2 * j) <= b) { off += 32 - 2 * j; j++; }
    int i = 2 * j + (b - off);
    const int m0 = i * BM;     // 128-row tile
    const int n0 = j * BN;     // 256-col tile

    const int t   = threadIdx.x;
    const int wid = t >> 5;
    const int wm  = wid >> 2;    // 0..1: 64-row slab
    const int wn  = wid & 3;     // 0..3: 64-col slab

    if (t < 128) {
        sqm[t] = g_sq[m0 + t];
        lbm[t] = g_lbl[m0 + t];
    }
    sqn[t] = g_sq[n0 + t];
    lbn[t] = g_lbl[n0 + t];

    const __nv_bfloat16* Am = g_xb + (size_t)m0 * d;
    const __nv_bfloat16* Bn = g_xb + (size_t)n0 * d;

    // load mapping per stage (16B chunks of 8 bf16):
    //   A: 1024 chunks -> thread t: row t>>1, chunk cols ((t&1)*4 + q), q=0..3
    //   B: 2048 chunks -> thread t: row t, all 8 chunks
    const int arow = t >> 1;
    const int ac0  = (t & 1) * 4;

    auto issue_stage = [&](int it, int buf) {
        const int k0 = it * KT;
        __nv_bfloat16* SA = stage + buf * STAGE_ELEMS;
        __nv_bfloat16* SB = SA + A_ELEMS;
        uint32_t sa = smem_u32(SA);
        uint32_t sb = smem_u32(SB);
#pragma unroll
        for (int q = 0; q < 4; q++) {
            int c8 = (ac0 + q) * 8;
            cp_async16(sa + (uint32_t)(arow * LDA + c8) * 2,
                       Am + (size_t)arow * d + k0 + c8);
        }
#pragma unroll
        for (int q = 0; q < 8; q++) {
            int c8 = q * 8;
            cp_async16(sb + (uint32_t)(t * LDA + c8) * 2,
                       Bn + (size_t)t * d + k0 + c8);
        }
        asm volatile("cp.async.commit_group;" ::: "memory");
    };

    wmma::fragment<wmma::accumulator, 16, 16, 16, float> cf[4][4];
#pragma unroll
    for (int a = 0; a < 4; a++)
#pragma unroll
        for (int c = 0; c < 4; c++) wmma::fill_fragment(cf[a][c], 0.0f);

    const int nIter = d / KT;
    issue_stage(0, 0);
    issue_stage(1, 1);

    int buf = 0;
    for (int it = 0; it < nIter; it++) {
        if (it + 1 < nIter)
            asm volatile("cp.async.wait_group 1;" ::: "memory");
        else
            asm volatile("cp.async.wait_group 0;" ::: "memory");
        __syncthreads();
        if (it + 2 < nIter) {
            int nb = buf + 2;
            if (nb >= NSTAGE) nb -= NSTAGE;
            issue_stage(it + 2, nb);
        }

        const __nv_bfloat16* As = stage + buf * STAGE_ELEMS;
        const __nv_bfloat16* Bs = As + A_ELEMS;
#pragma unroll
        for (int kk = 0; kk < KT; kk += 16) {
            wmma::fragment<wmma::matrix_a, 16, 16, 16, __nv_bfloat16,
                           wmma::row_major> af[4];
#pragma unroll
            for (int a = 0; a < 4; a++)
                wmma::load_matrix_sync(af[a],
                    As + (wm * 64 + a * 16) * LDA + kk, LDA);
#pragma unroll
            for (int c = 0; c < 4; c++) {
                wmma::fragment<wmma::matrix_b, 16, 16, 16, __nv_bfloat16,
                               wmma::col_major> bf;
                wmma::load_matrix_sync(bf,
                    Bs + (wn * 64 + c * 16) * LDA + kk, LDA);
#pragma unroll
                for (int a = 0; a < 4; a++)
                    wmma::mma_sync(cf[a][c], af[a], bf, cf[a][c]);
            }
        }
        if (++buf == NSTAGE) buf = 0;
    }

    // epilogue: stage buffers dead; reuse as C (128 x 256, stride LDC)
    __syncthreads();
#pragma unroll
    for (int a = 0; a < 4; a++)
#pragma unroll
        for (int c = 0; c < 4; c++)
            wmma::store_matrix_sync(
                Cs + (wm * 64 + a * 16) * LDC + wn * 64 + c * 16,
                cf[a][c], LDC, wmma::mem_row_major);
    __syncthreads();

    const float INF = __int_as_float(0x7F800000);

    // row anchors: thread pair per row, 128 cols each
    {
        const int r = t >> 1, h = t & 1;
        const float sm = sqm[r];
        const int   lm = lbm[r];
        float mp = 0.f, mn = INF;
        const float* crow = Cs + r * LDC + h * 128;
        const float* sq2  = sqn + h * 128;
        const int*   lb2  = lbn + h * 128;
#pragma unroll 16
        for (int c = 0; c < 128; c++) {
            float d2   = sm + sq2[c] - 2.f * crow[c];
            float dist = sqrtf(fmaxf(d2, 0.f));
            if (lm == lb2[c]) mp = fmaxf(mp, dist);
            else              mn = fminf(mn, dist);
        }
        mp = fmaxf(mp, __shfl_xor_sync(0xffffffffu, mp, 1));
        mn = fminf(mn, __shfl_xor_sync(0xffffffffu, mn, 1));
        if (h == 0) {
            atomicMax(&g_ap[m0 + r], __float_as_uint(mp));
            atomicMin(&g_an[m0 + r], __float_as_uint(mn));
        }
    }

    // column anchors: one thread per column, 128 rows
    {
        const int c = t;
        const float sc = sqn[c];
        const int   lc = lbn[c];
        float mp = 0.f, mn = INF;
#pragma unroll 16
        for (int r = 0; r < 128; r++) {
            float d2   = sc + sqm[r] - 2.f * Cs[r * LDC + c];
            float dist = sqrtf(fmaxf(d2, 0.f));
            if (lc == lbm[r]) mp = fmaxf(mp, dist);
            else              mn = fminf(mn, dist);
        }
        atomicMax(&g_ap[n0 + c], __float_as_uint(mp));
        atomicMin(&g_an[n0 + c], __float_as_uint(mn));
    }
}

// ---- kernel 3: mean hinge ----
__global__ void k_final(float* __restrict__ out, int n) {
    float s = 0.f;
    for (int i = threadIdx.x; i < n; i += blockDim.x) {
        float ap = __uint_as_float(g_ap[i]);
        float an = __uint_as_float(g_an[i]);
        s += fmaxf(ap - an + 0.3f, 0.f);
    }
    __shared__ float sh[32];
    for (int o = 16; o > 0; o >>= 1) s += __shfl_xor_sync(0xffffffffu, s, o);
    if ((threadIdx.x & 31) == 0) sh[threadIdx.x >> 5] = s;
    __syncthreads();
    if (threadIdx.x < 32) {
        float v = (threadIdx.x < (blockDim.x >> 5)) ? sh[threadIdx.x] : 0.f;
        for (int o = 16; o > 0; o >>= 1) v += __shfl_xor_sync(0xffffffffu, v, o);
        if (threadIdx.x == 0) out[0] = v / (float)n;
    }
}

extern "C" void kernel_launch(void* const* d_in, const int* in_sizes, int n_in,
                              void* d_out, int out_size) {
    const float* X = (const float*)d_in[0];
    const void*  Y = d_in[1];
    int n = in_sizes[1];                 // 4096
    int d = in_sizes[0] / n;             // 2048
    float* out = (float*)d_out;

    static int smem_set = 0;
    if (!smem_set) {
        cudaFuncSetAttribute(k_wmma,
                             cudaFuncAttributeMaxDynamicSharedMemorySize,
                             SMEM_BYTES);
        smem_set = 1;
    }

    k_detect<<<1, 32>>>((const int*)Y);
    k_rowsq<<<n, 256>>>(X, Y, n, d);
    k_tobf16<<<1024, 256>>>(X, (n * d) / 4);

    // blocks: (i,j) with i in [0,32), j in [0,16), i >= 2j  -> 272 blocks
    k_wmma<<<272, 256, SMEM_BYTES>>>(n, d);

    k_final<<<1, 256>>>(out, n);
}

// round 10
// speedup vs baseline: 1.0702x; 1.0702x over previous
#include <cuda_runtime.h>
#include <cuda_bf16.h>
#include <mma.h>
#include <cstdint>

using namespace nvcuda;

// ---------------------------------------------------------------------------
// TripletHardLoss: loss = mean(relu(max_{same}(dist) - min_{diff}(dist) + 0.3))
// dist[i][j] = sqrt(max(||xi||^2 + ||xj||^2 - 2 xi.xj, 0))
// bf16 WMMA Gram. R10: occupancy push — 3 CTAs/SM (24 warps), CTA tile
// 128x64, warp tile 32x32, 2-stage cp.async, triangular block coverage.
// ---------------------------------------------------------------------------

#define MAX_N 4096
#define MAX_D 2048

__device__ float           g_sq[MAX_N];
__device__ unsigned int    g_ap[MAX_N];
__device__ unsigned int    g_an[MAX_N];
__device__ int             g_lbl[MAX_N];
__device__ int             g_is64;
__device__ __nv_bfloat16   g_xb[(size_t)MAX_N * MAX_D];

// ---- tiling ----
#define BM 128
#define BN 64
#define KT 64                 // K per smem stage
#define LDA 72                // bf16 stage row stride (pad 8)
#define LDC 68                // fp32 C row stride
#define A_ELEMS (BM * LDA)                 // 9216
#define B_ELEMS (BN * LDA)                 // 4608
#define STAGE_ELEMS (A_ELEMS + B_ELEMS)    // 13824 elems = 27648 B
// smem: 2 stages = 55296B; C tile (128*68*4 = 34816B) aliases; meta after
#define OFF_META (2 * STAGE_ELEMS * 2)
#define SMEM_BYTES (OFF_META + (128 + 128 + 64 + 64) * 4)

__device__ __forceinline__ uint32_t smem_u32(const void* p) {
    uint32_t a;
    asm("{ .reg .u64 t; cvta.to.shared.u64 t, %1; cvt.u32.u64 %0, t; }"
        : "=r"(a) : "l"(p));
    return a;
}
__device__ __forceinline__ void cp_async16(uint32_t dst, const void* src) {
    asm volatile("cp.async.cg.shared.global [%0], [%1], 16;"
                 :: "r"(dst), "l"(src) : "memory");
}

// ---- kernel -1: detect label dtype ----
__global__ void k_detect(const int* __restrict__ Yi) {
    if (threadIdx.x == 0) {
        int nz = 0;
#pragma unroll
        for (int i = 0; i < 64; i++) nz |= Yi[2 * i + 1];
        g_is64 = (nz == 0) ? 1 : 0;
    }
}

// ---- kernel 0: row sum-of-squares + init + label narrow ----
__global__ void k_rowsq(const float* __restrict__ X,
                        const void* __restrict__ Y,
                        int n, int d) {
    int row = blockIdx.x;
    const float4* xr = reinterpret_cast<const float4*>(X + (size_t)row * d);
    int nv = d >> 2;
    float s = 0.f;
    for (int i = threadIdx.x; i < nv; i += blockDim.x) {
        float4 v = xr[i];
        s += v.x * v.x + v.y * v.y + v.z * v.z + v.w * v.w;
    }
    __shared__ float sh[32];
    for (int o = 16; o > 0; o >>= 1) s += __shfl_xor_sync(0xffffffffu, s, o);
    if ((threadIdx.x & 31) == 0) sh[threadIdx.x >> 5] = s;
    __syncthreads();
    if (threadIdx.x < 32) {
        float v = (threadIdx.x < (blockDim.x >> 5)) ? sh[threadIdx.x] : 0.f;
        for (int o = 16; o > 0; o >>= 1) v += __shfl_xor_sync(0xffffffffu, v, o);
        if (threadIdx.x == 0) {
            g_sq[row]  = v;
            g_ap[row]  = 0u;
            g_an[row]  = 0x7F800000u;
            g_lbl[row] = g_is64
                ? (int)reinterpret_cast<const long long*>(Y)[row]
                : reinterpret_cast<const int*>(Y)[row];
        }
    }
}

// ---- kernel 1: X (fp32) -> g_xb (bf16) ----
__global__ void k_tobf16(const float* __restrict__ X, int total4) {
    int stride = gridDim.x * blockDim.x;
    __nv_bfloat162* dst = reinterpret_cast<__nv_bfloat162*>(g_xb);
    for (int idx = blockIdx.x * blockDim.x + threadIdx.x; idx < total4;
         idx += stride) {
        float4 v = reinterpret_cast<const float4*>(X)[idx];
        dst[idx * 2 + 0] = __nv_bfloat162(__float2bfloat16(v.x),
                                          __float2bfloat16(v.y));
        dst[idx * 2 + 1] = __nv_bfloat162(__float2bfloat16(v.z),
                                          __float2bfloat16(v.w));
    }
}

// ---- kernel 2: 32x32-warp-tile bf16 WMMA Gram + masked max/min ----
__global__ __launch_bounds__(256, 3)
void k_wmma(int n, int d) {
    extern __shared__ __align__(16) char smem[];
    __nv_bfloat16* stage = reinterpret_cast<__nv_bfloat16*>(smem);
    float* Cs  = reinterpret_cast<float*>(smem);
    float* sqm = reinterpret_cast<float*>(smem + OFF_META);
    int*   lbm = reinterpret_cast<int*>(sqm + 128);
    float* sqn = reinterpret_cast<float*>(lbm + 128);
    int*   lbn = reinterpret_cast<int*>(sqn + 64);

    // block decode: (i,j) with j <= 2i+1, offset(i) = i*(i+1)
    int b = blockIdx.x;
    int i = (int)((sqrtf(4.0f * (float)b + 1.0f) - 1.0f) * 0.5f);
    while ((i + 1) * (i + 2) <= b) i++;
    while (i * (i + 1) > b) i--;
    int j = b - i * (i + 1);
    const int m0 = i * BM;     // 128-row tile
    const int n0 = j * BN;     // 64-col tile

    const int t   = threadIdx.x;
    const int wid = t >> 5;
    const int wm  = wid & 3;     // 0..3: 32-row slab
    const int wn  = wid >> 2;    // 0..1: 32-col slab

    if (t < 128) {
        sqm[t] = g_sq[m0 + t];
        lbm[t] = g_lbl[m0 + t];
    } else if (t < 192) {
        int c = t - 128;
        sqn[c] = g_sq[n0 + c];
        lbn[c] = g_lbl[n0 + c];
    }

    const __nv_bfloat16* Am = g_xb + (size_t)m0 * d;
    const __nv_bfloat16* Bn = g_xb + (size_t)n0 * d;

    // load mapping per stage (16B chunks of 8 bf16):
    //   A: 1024 chunks -> thread t: row t>>1, chunk cols (t&1)*4+q, q=0..3
    //   B: 512 chunks  -> thread t: row t>>2, chunk cols (t&3)*2+q, q=0..1
    const int arow = t >> 1;
    const int ac0  = (t & 1) * 4;
    const int brow = t >> 2;
    const int bc0  = (t & 3) * 2;

    auto issue_stage = [&](int it, int buf) {
        const int k0 = it * KT;
        __nv_bfloat16* SA = stage + buf * STAGE_ELEMS;
        __nv_bfloat16* SB = SA + A_ELEMS;
        uint32_t sa = smem_u32(SA);
        uint32_t sb = smem_u32(SB);
#pragma unroll
        for (int q = 0; q < 4; q++) {
            int c8 = (ac0 + q) * 8;
            cp_async16(sa + (uint32_t)(arow * LDA + c8) * 2,
                       Am + (size_t)arow * d + k0 + c8);
        }
#pragma unroll
        for (int q = 0; q < 2; q++) {
            int c8 = (bc0 + q) * 8;
            cp_async16(sb + (uint32_t)(brow * LDA + c8) * 2,
                       Bn + (size_t)brow * d + k0 + c8);
        }
        asm volatile("cp.async.commit_group;" ::: "memory");
    };

    wmma::fragment<wmma::accumulator, 16, 16, 16, float> cf[2][2];
#pragma unroll
    for (int a = 0; a < 2; a++)
#pragma unroll
        for (int c = 0; c < 2; c++) wmma::fill_fragment(cf[a][c], 0.0f);

    const int nIter = d / KT;
    issue_stage(0, 0);

    int buf = 0;
    for (int it = 0; it < nIter; it++) {
        asm volatile("cp.async.wait_group 0;" ::: "memory");
        // barrier: stage `it` visible to all warps AND compute(it-1) finished
        // everywhere, so buf^1 is free to refill.
        __syncthreads();
        if (it + 1 < nIter) issue_stage(it + 1, buf ^ 1);

        const __nv_bfloat16* As = stage + buf * STAGE_ELEMS;
        const __nv_bfloat16* Bs = As + A_ELEMS;
#pragma unroll
        for (int kk = 0; kk < KT; kk += 16) {
            wmma::fragment<wmma::matrix_a, 16, 16, 16, __nv_bfloat16,
                           wmma::row_major> af[2];
#pragma unroll
            for (int a = 0; a < 2; a++)
                wmma::load_matrix_sync(af[a],
                    As + (wm * 32 + a * 16) * LDA + kk, LDA);
#pragma unroll
            for (int c = 0; c < 2; c++) {
                wmma::fragment<wmma::matrix_b, 16, 16, 16, __nv_bfloat16,
                               wmma::col_major> bf;
                wmma::load_matrix_sync(bf,
                    Bs + (wn * 32 + c * 16) * LDA + kk, LDA);
#pragma unroll
                for (int a = 0; a < 2; a++)
                    wmma::mma_sync(cf[a][c], af[a], bf, cf[a][c]);
            }
        }
        buf ^= 1;
    }

    // epilogue: stage buffers dead; reuse as C (128 x 64, stride LDC)
    __syncthreads();
#pragma unroll
    for (int a = 0; a < 2; a++)
#pragma unroll
        for (int c = 0; c < 2; c++)
            wmma::store_matrix_sync(
                Cs + (wm * 32 + a * 16) * LDC + wn * 32 + c * 16,
                cf[a][c], LDC, wmma::mem_row_major);
    __syncthreads();

    const float INF = __int_as_float(0x7F800000);

    // row anchors: 2 threads per row, 32 cols each
    {
        const int r = t >> 1, h = t & 1;
        const float sm = sqm[r];
        const int   lm = lbm[r];
        float mp = 0.f, mn = INF;
        const float* crow = Cs + r * LDC + h * 32;
        const float* sq2  = sqn + h * 32;
        const int*   lb2  = lbn + h * 32;
#pragma unroll 8
        for (int c = 0; c < 32; c++) {
            float d2   = sm + sq2[c] - 2.f * crow[c];
            float dist = sqrtf(fmaxf(d2, 0.f));
            if (lm == lb2[c]) mp = fmaxf(mp, dist);
            else              mn = fminf(mn, dist);
        }
        mp = fmaxf(mp, __shfl_xor_sync(0xffffffffu, mp, 1));
        mn = fminf(mn, __shfl_xor_sync(0xffffffffu, mn, 1));
        if (h == 0) {
            atomicMax(&g_ap[m0 + r], __float_as_uint(mp));
            atomicMin(&g_an[m0 + r], __float_as_uint(mn));
        }
    }

    // column anchors: 4 threads per column, 32 rows each
    {
        const int c = t >> 2, h = t & 3;
        const float sc = sqn[c];
        const int   lc = lbn[c];
        float mp = 0.f, mn = INF;
        const float* cc  = Cs + (h * 32) * LDC + c;
        const float* sq2 = sqm + h * 32;
        const int*   lb2 = lbm + h * 32;
#pragma unroll 8
        for (int r = 0; r < 32; r++) {
            float d2   = sc + sq2[r] - 2.f * cc[r * LDC];
            float dist = sqrtf(fmaxf(d2, 0.f));
            if (lc == lb2[r]) mp = fmaxf(mp, dist);
            else              mn = fminf(mn, dist);
        }
#pragma unroll
        for (int o = 1; o <= 2; o <<= 1) {
            mp = fmaxf(mp, __shfl_xor_sync(0xffffffffu, mp, o));
            mn = fminf(mn, __shfl_xor_sync(0xffffffffu, mn, o));
        }
        if (h == 0) {
            atomicMax(&g_ap[n0 + c], __float_as_uint(mp));
            atomicMin(&g_an[n0 + c], __float_as_uint(mn));
        }
    }
}

// ---- kernel 3: mean hinge ----
__global__ void k_final(float* __restrict__ out, int n) {
    float s = 0.f;
    for (int i = threadIdx.x; i < n; i += blockDim.x) {
        float ap = __uint_as_float(g_ap[i]);
        float an = __uint_as_float(g_an[i]);
        s += fmaxf(ap - an + 0.3f, 0.f);
    }
    __shared__ float sh[32];
    for (int o = 16; o > 0; o >>= 1) s += __shfl_xor_sync(0xffffffffu, s, o);
    if ((threadIdx.x & 31) == 0) sh[threadIdx.x >> 5] = s;
    __syncthreads();
    if (threadIdx.x < 32) {
        float v = (threadIdx.x < (blockDim.x >> 5)) ? sh[threadIdx.x] : 0.f;
        for (int o = 16; o > 0; o >>= 1) v += __shfl_xor_sync(0xffffffffu, v, o);
        if (threadIdx.x == 0) out[0] = v / (float)n;
    }
}

extern "C" void kernel_launch(void* const* d_in, const int* in_sizes, int n_in,
                              void* d_out, int out_size) {
    const float* X = (const float*)d_in[0];
    const void*  Y = d_in[1];
    int n = in_sizes[1];                 // 4096
    int d = in_sizes[0] / n;             // 2048
    float* out = (float*)d_out;

    static int smem_set = 0;
    if (!smem_set) {
        cudaFuncSetAttribute(k_wmma,
                             cudaFuncAttributeMaxDynamicSharedMemorySize,
                             SMEM_BYTES);
        smem_set = 1;
    }

    k_detect<<<1, 32>>>((const int*)Y);
    k_rowsq<<<n, 256>>>(X, Y, n, d);
    k_tobf16<<<1024, 256>>>(X, (n * d) / 4);

    // blocks: (i,j), i in [0,32), j <= 2i+1 -> sum(2i+2) = 1056 blocks
    k_wmma<<<1056, 256, SMEM_BYTES>>>(n, d);

    k_final<<<1, 256>>>(out, n);
}

// round 11
// speedup vs baseline: 1.2772x; 1.1934x over previous
#include <cuda_runtime.h>
#include <cuda_bf16.h>
#include <cstdint>

// ---------------------------------------------------------------------------
// TripletHardLoss: loss = mean(relu(max_{same}(dist) - min_{diff}(dist) + 0.3))
// dist[i][j] = sqrt(max(||xi||^2 + ||xj||^2 - 2 xi.xj, 0))
// R11: raw PTX mma.sync.m16n8k16 + ldmatrix with explicit register
// double-buffering of fragments (WMMA API + 128-reg cap was blocking
// software pipelining). 128x128 triangle tiles, 32x64 warp tiles, 3-stage
// cp.async, 2 CTAs/SM. Preprocessing fused into one pass.
// ---------------------------------------------------------------------------

#define MAX_N 4096
#define MAX_D 2048

__device__ float           g_sq[MAX_N];
__device__ unsigned int    g_ap[MAX_N];
__device__ unsigned int    g_an[MAX_N];
__device__ int             g_lbl[MAX_N];
__device__ int             g_is64;
__device__ __nv_bfloat16   g_xb[(size_t)MAX_N * MAX_D];

// ---- tiling ----
#define BM 128
#define BN 128
#define KT 64                 // K per smem stage
#define LDA 72                // bf16 stage row stride (pad 8), 144B
#define LDC 132               // fp32 C row stride
#define NSTAGE 3
#define A_ELEMS (BM * LDA)                // 9216 bf16 per matrix
#define STAGE_ELEMS (2 * A_ELEMS)         // A+B per stage
#define STAGE_BYTES (STAGE_ELEMS * 2)     // 36864
#define OFF_META (NSTAGE * STAGE_BYTES)   // 110592
#define SMEM_BYTES (OFF_META + 4 * 128 * 4)

__device__ __forceinline__ uint32_t smem_u32(const void* p) {
    uint32_t a;
    asm("{ .reg .u64 t; cvta.to.shared.u64 t, %1; cvt.u32.u64 %0, t; }"
        : "=r"(a) : "l"(p));
    return a;
}
__device__ __forceinline__ void cp_async16(uint32_t dst, const void* src) {
    asm volatile("cp.async.cg.shared.global [%0], [%1], 16;"
                 :: "r"(dst), "l"(src) : "memory");
}
__device__ __forceinline__ void ldsm4(uint32_t addr, uint32_t* r) {
    asm volatile("ldmatrix.sync.aligned.m8n8.x4.shared.b16 {%0,%1,%2,%3}, [%4];"
                 : "=r"(r[0]), "=r"(r[1]), "=r"(r[2]), "=r"(r[3])
                 : "r"(addr));
}
__device__ __forceinline__ void mma16816(float* c, const uint32_t* a,
                                         uint32_t b0, uint32_t b1) {
    asm volatile(
        "mma.sync.aligned.m16n8k16.row.col.f32.bf16.bf16.f32 "
        "{%0,%1,%2,%3}, {%4,%5,%6,%7}, {%8,%9}, {%0,%1,%2,%3};"
        : "+f"(c[0]), "+f"(c[1]), "+f"(c[2]), "+f"(c[3])
        : "r"(a[0]), "r"(a[1]), "r"(a[2]), "r"(a[3]), "r"(b0), "r"(b1));
}

// ---- kernel -1: detect label dtype ----
__global__ void k_detect(const int* __restrict__ Yi) {
    if (threadIdx.x == 0) {
        int nz = 0;
#pragma unroll
        for (int i = 0; i < 64; i++) nz |= Yi[2 * i + 1];
        g_is64 = (nz == 0) ? 1 : 0;
    }
}

// ---- kernel 0: fused row sum-of-squares + bf16 convert + init ----
__global__ void k_prep(const float* __restrict__ X,
                       const void* __restrict__ Y,
                       int n, int d) {
    int row = blockIdx.x;
    const float4* xr = reinterpret_cast<const float4*>(X + (size_t)row * d);
    __nv_bfloat162* dst =
        reinterpret_cast<__nv_bfloat162*>(g_xb + (size_t)row * d);
    int nv = d >> 2;
    float s = 0.f;
    for (int i = threadIdx.x; i < nv; i += blockDim.x) {
        float4 v = xr[i];
        s += v.x * v.x + v.y * v.y + v.z * v.z + v.w * v.w;
        dst[i * 2 + 0] = __nv_bfloat162(__float2bfloat16(v.x),
                                        __float2bfloat16(v.y));
        dst[i * 2 + 1] = __nv_bfloat162(__float2bfloat16(v.z),
                                        __float2bfloat16(v.w));
    }
    __shared__ float sh[32];
    for (int o = 16; o > 0; o >>= 1) s += __shfl_xor_sync(0xffffffffu, s, o);
    if ((threadIdx.x & 31) == 0) sh[threadIdx.x >> 5] = s;
    __syncthreads();
    if (threadIdx.x < 32) {
        float v = (threadIdx.x < (blockDim.x >> 5)) ? sh[threadIdx.x] : 0.f;
        for (int o = 16; o > 0; o >>= 1) v += __shfl_xor_sync(0xffffffffu, v, o);
        if (threadIdx.x == 0) {
            g_sq[row]  = v;
            g_ap[row]  = 0u;
            g_an[row]  = 0x7F800000u;
            g_lbl[row] = g_is64
                ? (int)reinterpret_cast<const long long*>(Y)[row]
                : reinterpret_cast<const int*>(Y)[row];
        }
    }
}

// ---- kernel 1: raw-mma triangular Gram + masked row/col max/min ----
__global__ __launch_bounds__(256, 2)
void k_mma(int n, int d) {
    extern __shared__ __align__(16) char smem[];
    const uint32_t sbase = smem_u32(smem);
    float* Cs  = reinterpret_cast<float*>(smem);
    float* sqm = reinterpret_cast<float*>(smem + OFF_META);
    float* sqn = sqm + 128;
    int*   lbm = reinterpret_cast<int*>(sqn + 128);
    int*   lbn = lbm + 128;

    // triangular tile decode: block b -> (i >= j)
    int b = blockIdx.x;
    int i = (int)((sqrtf(8.0f * (float)b + 1.0f) - 1.0f) * 0.5f);
    while ((i + 1) * (i + 2) / 2 <= b) i++;
    while (i * (i + 1) / 2 > b) i--;
    int j = b - i * (i + 1) / 2;
    const int m0 = i * BM;
    const int n0 = j * BN;

    const int t    = threadIdx.x;
    const int wid  = t >> 5;
    const int lane = t & 31;
    const int wm   = wid & 3;     // 32-row slab
    const int wn   = wid >> 2;    // 64-col slab

    if (t < 128) {
        sqm[t] = g_sq[m0 + t];
        lbm[t] = g_lbl[m0 + t];
    } else {
        int c = t - 128;
        sqn[c] = g_sq[n0 + c];
        lbn[c] = g_lbl[n0 + c];
    }

    const __nv_bfloat16* Am = g_xb + (size_t)m0 * d;
    const __nv_bfloat16* Bn = g_xb + (size_t)n0 * d;

    // cp.async mapping: row=t>>1, cols (t&1)*32 + q*8, q=0..3 (full coverage)
    const int lrow = t >> 1;
    const int lc0  = (t & 1) * 32;

    auto issue_stage = [&](int it, int buf) {
        const int k0 = it * KT;
        uint32_t sa = sbase + buf * STAGE_BYTES;
        uint32_t sb = sa + A_ELEMS * 2;
#pragma unroll
        for (int q = 0; q < 4; q++) {
            int c8 = lc0 + q * 8;
            uint32_t so = (uint32_t)(lrow * LDA + c8) * 2;
            cp_async16(sa + so, Am + (size_t)lrow * d + k0 + c8);
            cp_async16(sb + so, Bn + (size_t)lrow * d + k0 + c8);
        }
        asm volatile("cp.async.commit_group;" ::: "memory");
    };

    // ldmatrix lane offsets (bytes within stage), canonical x4 layouts:
    // A: lanes 0-7 m0-7 k0 | 8-15 m8-15 k0 | 16-23 m0-7 k8 | 24-31 m8-15 k8
    // B: lanes 0-7 n0-7 k0 | 8-15 n0-7 k8 | 16-23 n8-15 k0 | 24-31 n8-15 k8
    const int aRow = (lane & 7) + ((lane >> 3) & 1) * 8;
    const int aK   = (lane >> 4) * 8;
    const int bRow = (lane & 7) + (lane >> 4) * 8;
    const int bK   = ((lane >> 3) & 1) * 8;
    uint32_t aOff[2], bOff[4];
#pragma unroll
    for (int mf = 0; mf < 2; mf++)
        aOff[mf] = (uint32_t)((wm * 32 + mf * 16 + aRow) * LDA + aK) * 2;
#pragma unroll
    for (int nq = 0; nq < 4; nq++)
        bOff[nq] = (uint32_t)((wn * 64 + nq * 16 + bRow) * LDA + bK) * 2
                   + A_ELEMS * 2;

    float acc[2][8][4];
#pragma unroll
    for (int mf = 0; mf < 2; mf++)
#pragma unroll
        for (int nf = 0; nf < 8; nf++)
#pragma unroll
            for (int r = 0; r < 4; r++) acc[mf][nf][r] = 0.f;

    const int nIter = d / KT;
    issue_stage(0, 0);
    issue_stage(1, 1);

    int buf = 0;
    for (int it = 0; it < nIter; it++) {
        if (it + 1 < nIter)
            asm volatile("cp.async.wait_group 1;" ::: "memory");
        else
            asm volatile("cp.async.wait_group 0;" ::: "memory");
        __syncthreads();
        if (it + 2 < nIter) {
            int nb = buf + 2;
            if (nb >= NSTAGE) nb -= NSTAGE;
            issue_stage(it + 2, nb);
        }

        const uint32_t sg = sbase + buf * STAGE_BYTES;

        // register double-buffered fragments across the 4 k16 slices
        uint32_t a[2][2][4];   // [pipe][mf][reg]
        uint32_t bb[2][4][4];  // [pipe][nq][reg]
        ldsm4(sg + aOff[0], a[0][0]);
        ldsm4(sg + aOff[1], a[0][1]);
#pragma unroll
        for (int nq = 0; nq < 4; nq++) ldsm4(sg + bOff[nq], bb[0][nq]);

#pragma unroll
        for (int s = 0; s < 4; s++) {
            const int cu = s & 1;
            const int nx = cu ^ 1;
            if (s < 3) {
                const uint32_t kb = (uint32_t)(s + 1) * 16 * 2;
                ldsm4(sg + aOff[0] + kb, a[nx][0]);
                ldsm4(sg + aOff[1] + kb, a[nx][1]);
#pragma unroll
                for (int nq = 0; nq < 4; nq++)
                    ldsm4(sg + bOff[nq] + kb, bb[nx][nq]);
            }
#pragma unroll
            for (int mf = 0; mf < 2; mf++)
#pragma unroll
                for (int nq = 0; nq < 4; nq++) {
                    mma16816(acc[mf][nq * 2 + 0], a[cu][mf],
                             bb[cu][nq][0], bb[cu][nq][1]);
                    mma16816(acc[mf][nq * 2 + 1], a[cu][mf],
                             bb[cu][nq][2], bb[cu][nq][3]);
                }
        }
        if (++buf == NSTAGE) buf = 0;
    }

    // epilogue: stage buffers dead; write C (128 x 128, stride LDC)
    __syncthreads();
    {
        const int cr = lane >> 2;          // row within m16 frag
        const int cc = (lane & 3) * 2;     // col within n8 frag
#pragma unroll
        for (int mf = 0; mf < 2; mf++)
#pragma unroll
            for (int nf = 0; nf < 8; nf++) {
                int row = wm * 32 + mf * 16 + cr;
                int col = wn * 64 + nf * 8 + cc;
                float* p = Cs + row * LDC + col;
                p[0] = acc[mf][nf][0];
                p[1] = acc[mf][nf][1];
                p[8 * LDC + 0] = acc[mf][nf][2];
                p[8 * LDC + 1] = acc[mf][nf][3];
            }
    }
    __syncthreads();

    const float INF = __int_as_float(0x7F800000);

    // row anchors: thread pair per row, 64 cols each
    {
        const int r = t >> 1, h = t & 1;
        const float sm = sqm[r];
        const int   lm = lbm[r];
        float mp = 0.f, mn = INF;
        const float* crow = Cs + r * LDC + h * 64;
        const float* sq2  = sqn + h * 64;
        const int*   lb2  = lbn + h * 64;
#pragma unroll 16
        for (int c = 0; c < 64; c++) {
            float d2   = sm + sq2[c] - 2.f * crow[c];
            float dist = sqrtf(fmaxf(d2, 0.f));
            if (lm == lb2[c]) mp = fmaxf(mp, dist);
            else              mn = fminf(mn, dist);
        }
        mp = fmaxf(mp, __shfl_xor_sync(0xffffffffu, mp, 1));
        mn = fminf(mn, __shfl_xor_sync(0xffffffffu, mn, 1));
        if (h == 0) {
            atomicMax(&g_ap[m0 + r], __float_as_uint(mp));
            atomicMin(&g_an[m0 + r], __float_as_uint(mn));
        }
    }

    // column anchors (off-diagonal coverage of the symmetric half)
    if (m0 != n0) {
        const int c = t >> 1, h = t & 1;
        const float sc = sqn[c];
        const int   lc = lbn[c];
        float mp = 0.f, mn = INF;
        const float* ccol = Cs + (h * 64) * LDC + c;
        const float* sq2  = sqm + h * 64;
        const int*   lb2  = lbm + h * 64;
#pragma unroll 16
        for (int r = 0; r < 64; r++) {
            float d2   = sc + sq2[r] - 2.f * ccol[r * LDC];
            float dist = sqrtf(fmaxf(d2, 0.f));
            if (lc == lb2[r]) mp = fmaxf(mp, dist);
            else              mn = fminf(mn, dist);
        }
        mp = fmaxf(mp, __shfl_xor_sync(0xffffffffu, mp, 1));
        mn = fminf(mn, __shfl_xor_sync(0xffffffffu, mn, 1));
        if (h == 0) {
            atomicMax(&g_ap[n0 + c], __float_as_uint(mp));
            atomicMin(&g_an[n0 + c], __float_as_uint(mn));
        }
    }
}

// ---- kernel 2: mean hinge ----
__global__ void k_final(float* __restrict__ out, int n) {
    float s = 0.f;
    for (int i = threadIdx.x; i < n; i += blockDim.x) {
        float ap = __uint_as_float(g_ap[i]);
        float an = __uint_as_float(g_an[i]);
        s += fmaxf(ap - an + 0.3f, 0.f);
    }
    __shared__ float sh[32];
    for (int o = 16; o > 0; o >>= 1) s += __shfl_xor_sync(0xffffffffu, s, o);
    if ((threadIdx.x & 31) == 0) sh[threadIdx.x >> 5] = s;
    __syncthreads();
    if (threadIdx.x < 32) {
        float v = (threadIdx.x < (blockDim.x >> 5)) ? sh[threadIdx.x] : 0.f;
        for (int o = 16; o > 0; o >>= 1) v += __shfl_xor_sync(0xffffffffu, v, o);
        if (threadIdx.x == 0) out[0] = v / (float)n;
    }
}

extern "C" void kernel_launch(void* const* d_in, const int* in_sizes, int n_in,
                              void* d_out, int out_size) {
    const float* X = (const float*)d_in[0];
    const void*  Y = d_in[1];
    int n = in_sizes[1];                 // 4096
    int d = in_sizes[0] / n;             // 2048
    float* out = (float*)d_out;

    static int smem_set = 0;
    if (!smem_set) {
        cudaFuncSetAttribute(k_mma,
                             cudaFuncAttributeMaxDynamicSharedMemorySize,
                             SMEM_BYTES);
        smem_set = 1;
    }

    k_detect<<<1, 32>>>((const int*)Y);
    k_prep<<<n, 256>>>(X, Y, n, d);

    int nt = n / BM;
    int nblocks = nt * (nt + 1) / 2;     // 528
    k_mma<<<nblocks, 256, SMEM_BYTES>>>(n, d);

    k_final<<<1, 256>>>(out, n);
}